// round 1
// baseline (speedup 1.0000x reference)
#include <cuda_runtime.h>

#define S_LEN   2048
#define BATCH   2
#define DMODEL  1024
#define NHEADS  16
#define DK      64
#define MTOT    (BATCH * S_LEN)   // 4096

// ---------------- scratch (static device globals; no dynamic allocation) ----
__device__ float g_Q[BATCH * NHEADS * S_LEN * DK];    // (b,h,s,d)
__device__ float g_K[BATCH * NHEADS * S_LEN * DK];
__device__ float g_V[BATCH * NHEADS * S_LEN * DK];
__device__ float g_ctx[MTOT * DMODEL];                // (b,s,h*d)

// ---------------------------------------------------------------------------
// C = A (M x K, row-major) * W^T (W is N x K row-major) + bias
// MODE 0: write C row-major (m, n)
// MODE 1: write into head-major layout (b, h, s, d) where m=b*S+s, n=h*64+d
// Tiles: 128x128x16, 256 threads, 8x8 per thread.
// ---------------------------------------------------------------------------
template <int MODE>
__global__ void __launch_bounds__(256, 2) gemm_nt_kernel(
    const float* __restrict__ A, const float* __restrict__ W,
    const float* __restrict__ bias, float* __restrict__ C)
{
    __shared__ float As[16][136];   // [k][m], padded pitch (bank stride 8)
    __shared__ float Ws[16][136];   // [k][n]

    const int m0 = blockIdx.y * 128;
    const int n0 = blockIdx.x * 128;
    const int tid = threadIdx.x;
    const int tx = tid & 15;        // n group
    const int ty = tid >> 4;        // m group

    float acc[8][8];
#pragma unroll
    for (int i = 0; i < 8; ++i)
#pragma unroll
        for (int j = 0; j < 8; ++j) acc[i][j] = 0.0f;

    for (int kt = 0; kt < DMODEL; kt += 16) {
#pragma unroll
        for (int i = 0; i < 2; ++i) {
            int v   = tid * 2 + i;          // 0..511 float4 slots
            int row = v >> 2;               // 0..127
            int kk  = (v & 3) << 2;         // 0,4,8,12
            float4 a = *(const float4*)(A + (size_t)(m0 + row) * DMODEL + kt + kk);
            As[kk + 0][row] = a.x; As[kk + 1][row] = a.y;
            As[kk + 2][row] = a.z; As[kk + 3][row] = a.w;
            float4 w = *(const float4*)(W + (size_t)(n0 + row) * DMODEL + kt + kk);
            Ws[kk + 0][row] = w.x; Ws[kk + 1][row] = w.y;
            Ws[kk + 2][row] = w.z; Ws[kk + 3][row] = w.w;
        }
        __syncthreads();

#pragma unroll
        for (int kk = 0; kk < 16; ++kk) {
            float4 a0 = *(float4*)&As[kk][ty * 8];
            float4 a1 = *(float4*)&As[kk][ty * 8 + 4];
            float4 b0 = *(float4*)&Ws[kk][tx * 8];
            float4 b1 = *(float4*)&Ws[kk][tx * 8 + 4];
            float ra[8] = {a0.x, a0.y, a0.z, a0.w, a1.x, a1.y, a1.z, a1.w};
            float rb[8] = {b0.x, b0.y, b0.z, b0.w, b1.x, b1.y, b1.z, b1.w};
#pragma unroll
            for (int i = 0; i < 8; ++i)
#pragma unroll
                for (int j = 0; j < 8; ++j) acc[i][j] += ra[i] * rb[j];
        }
        __syncthreads();
    }

#pragma unroll
    for (int i = 0; i < 8; ++i) {
        int m = m0 + ty * 8 + i;
#pragma unroll
        for (int j = 0; j < 8; ++j) {
            int n = n0 + tx * 8 + j;
            float val = acc[i][j] + bias[n];
            if (MODE == 0) {
                C[(size_t)m * DMODEL + n] = val;
            } else {
                int b = m >> 11;          // m / 2048
                int s = m & 2047;
                int h = n >> 6;           // n / 64
                int d = n & 63;
                C[(((size_t)(b * NHEADS + h) * S_LEN + s) * DK) + d] = val;
            }
        }
    }
}

// ---------------------------------------------------------------------------
// Flash attention for one (b, h, 64-row q tile). 256 threads.
// Smem: Qt [d][q] (64x64), KPt dual-use: K as [d][k] then P as [k][q],
//       Vs [k][d]. Exactly 48 KB static shared.
// Thread (ty,tx), 16x16: owns q rows ty*4..+3 and k (resp. d) cols tx*4..+3.
// ---------------------------------------------------------------------------
__global__ void __launch_bounds__(256, 2) attn_kernel(
    const float* __restrict__ Q, const float* __restrict__ K,
    const float* __restrict__ V, const int* __restrict__ mask,
    float* __restrict__ ctx)
{
    __shared__ float Qt[DK][64];     // [d][q]
    __shared__ float KPt[64][64];    // K: [d][k]  /  P: [k][q]
    __shared__ float Vs[64][DK];     // [k][d]

    const int qt = blockIdx.x;       // 0..31
    const int h  = blockIdx.y;
    const int b  = blockIdx.z;
    const int q0 = qt * 64;
    const size_t base = (size_t)(b * NHEADS + h) * S_LEN * DK;

    const int tid = threadIdx.x;
    const int tx = tid & 15;
    const int ty = tid >> 4;

    // Load Q tile transposed: Qt[d][q]
#pragma unroll
    for (int i = 0; i < 4; ++i) {
        int v = tid * 4 + i;             // 0..1023 float4 slots
        int q = v >> 4;                  // 0..63
        int d = (v & 15) << 2;           // 0..60
        float4 x = *(const float4*)(Q + base + (size_t)(q0 + q) * DK + d);
        Qt[d + 0][q] = x.x; Qt[d + 1][q] = x.y;
        Qt[d + 2][q] = x.z; Qt[d + 3][q] = x.w;
    }

    float m_i[4], l_i[4], o[4][4];
#pragma unroll
    for (int qi = 0; qi < 4; ++qi) {
        m_i[qi] = -1.0e30f;
        l_i[qi] = 0.0f;
#pragma unroll
        for (int dj = 0; dj < 4; ++dj) o[qi][dj] = 0.0f;
    }

    for (int k0 = 0; k0 < S_LEN; k0 += 64) {
        // Load K transposed -> KPt[d][k]; V straight -> Vs[k][d]
#pragma unroll
        for (int i = 0; i < 4; ++i) {
            int v = tid * 4 + i;
            int r = v >> 4;              // k row
            int d = (v & 15) << 2;
            float4 kk = *(const float4*)(K + base + (size_t)(k0 + r) * DK + d);
            KPt[d + 0][r] = kk.x; KPt[d + 1][r] = kk.y;
            KPt[d + 2][r] = kk.z; KPt[d + 3][r] = kk.w;
            float4 vv = *(const float4*)(V + base + (size_t)(k0 + r) * DK + d);
            *(float4*)&Vs[r][d] = vv;
        }
        // mask for this thread's k columns (int4-aligned)
        int4 mk = *(const int4*)(mask + b * S_LEN + k0 + tx * 4);
        __syncthreads();

        // scores S[q][k] over d
        float s[4][4];
#pragma unroll
        for (int qi = 0; qi < 4; ++qi)
#pragma unroll
            for (int kj = 0; kj < 4; ++kj) s[qi][kj] = 0.0f;
#pragma unroll
        for (int d = 0; d < DK; ++d) {
            float4 rq = *(float4*)&Qt[d][ty * 4];
            float4 rk = *(float4*)&KPt[d][tx * 4];
            float fq[4] = {rq.x, rq.y, rq.z, rq.w};
            float fk[4] = {rk.x, rk.y, rk.z, rk.w};
#pragma unroll
            for (int qi = 0; qi < 4; ++qi)
#pragma unroll
                for (int kj = 0; kj < 4; ++kj) s[qi][kj] += fq[qi] * fk[kj];
        }
        const float scale = 0.125f;     // 1/sqrt(64)
        int msk[4] = {mk.x, mk.y, mk.z, mk.w};
#pragma unroll
        for (int qi = 0; qi < 4; ++qi)
#pragma unroll
            for (int kj = 0; kj < 4; ++kj) {
                float v = s[qi][kj] * scale;
                s[qi][kj] = (msk[kj] == 0) ? -1.0e9f : v;
            }

        // online softmax per q-row (row spread over 16 lanes of a half-warp)
        float alpha[4];
#pragma unroll
        for (int qi = 0; qi < 4; ++qi) {
            float mx = fmaxf(fmaxf(s[qi][0], s[qi][1]), fmaxf(s[qi][2], s[qi][3]));
#pragma unroll
            for (int off = 8; off >= 1; off >>= 1)
                mx = fmaxf(mx, __shfl_xor_sync(0xffffffffu, mx, off));
            float mn = fmaxf(m_i[qi], mx);
            float rs = 0.0f;
#pragma unroll
            for (int kj = 0; kj < 4; ++kj) {
                s[qi][kj] = __expf(s[qi][kj] - mn);
                rs += s[qi][kj];
            }
#pragma unroll
            for (int off = 8; off >= 1; off >>= 1)
                rs += __shfl_xor_sync(0xffffffffu, rs, off);
            alpha[qi] = __expf(m_i[qi] - mn);
            l_i[qi] = l_i[qi] * alpha[qi] + rs;
            m_i[qi] = mn;
        }

        __syncthreads();   // all K reads done before P overwrites KPt
        // write P transposed: KPt[k][q]
#pragma unroll
        for (int kj = 0; kj < 4; ++kj) {
            *(float4*)&KPt[tx * 4 + kj][ty * 4] =
                make_float4(s[0][kj], s[1][kj], s[2][kj], s[3][kj]);
        }
        __syncthreads();

        // rescale O, then O += P^T-view * V
#pragma unroll
        for (int qi = 0; qi < 4; ++qi)
#pragma unroll
            for (int dj = 0; dj < 4; ++dj) o[qi][dj] *= alpha[qi];
#pragma unroll
        for (int k = 0; k < 64; ++k) {
            float4 rp = *(float4*)&KPt[k][ty * 4];
            float4 rv = *(float4*)&Vs[k][tx * 4];
            float fp[4] = {rp.x, rp.y, rp.z, rp.w};
            float fv[4] = {rv.x, rv.y, rv.z, rv.w};
#pragma unroll
            for (int qi = 0; qi < 4; ++qi)
#pragma unroll
                for (int dj = 0; dj < 4; ++dj) o[qi][dj] += fp[qi] * fv[dj];
        }
        __syncthreads();   // before next tile overwrites KPt/Vs
    }

    // epilogue: normalize and write context in (b, s, h, d) layout
#pragma unroll
    for (int qi = 0; qi < 4; ++qi) {
        float inv = 1.0f / l_i[qi];
        int q = q0 + ty * 4 + qi;
        float4 out = make_float4(o[qi][0] * inv, o[qi][1] * inv,
                                 o[qi][2] * inv, o[qi][3] * inv);
        *(float4*)(ctx + (size_t)(b * S_LEN + q) * DMODEL + h * DK + tx * 4) = out;
    }
}

// ---------------------------------------------------------------------------
extern "C" void kernel_launch(void* const* d_in, const int* in_sizes, int n_in,
                              void* d_out, int out_size)
{
    const float* query = (const float*)d_in[0];
    const float* key   = (const float*)d_in[1];
    const float* value = (const float*)d_in[2];
    const int*   mask  = (const int*)d_in[3];
    const float* Wq = (const float*)d_in[4];
    const float* bq = (const float*)d_in[5];
    const float* Wk = (const float*)d_in[6];
    const float* bk = (const float*)d_in[7];
    const float* Wv = (const float*)d_in[8];
    const float* bv = (const float*)d_in[9];
    const float* Wo = (const float*)d_in[10];
    const float* bo = (const float*)d_in[11];
    float* out = (float*)d_out;

    float *Qd, *Kd, *Vd, *Cd;
    cudaGetSymbolAddress((void**)&Qd, g_Q);
    cudaGetSymbolAddress((void**)&Kd, g_K);
    cudaGetSymbolAddress((void**)&Vd, g_V);
    cudaGetSymbolAddress((void**)&Cd, g_ctx);

    dim3 gemm_grid(DMODEL / 128, MTOT / 128);   // (8, 32)
    gemm_nt_kernel<1><<<gemm_grid, 256>>>(query, Wq, bq, Qd);
    gemm_nt_kernel<1><<<gemm_grid, 256>>>(key,   Wk, bk, Kd);
    gemm_nt_kernel<1><<<gemm_grid, 256>>>(value, Wv, bv, Vd);

    dim3 attn_grid(S_LEN / 64, NHEADS, BATCH);  // (32, 16, 2)
    attn_kernel<<<attn_grid, 256>>>(Qd, Kd, Vd, mask, Cd);

    gemm_nt_kernel<0><<<gemm_grid, 256>>>(Cd, Wo, bo, out);
}

// round 4
// speedup vs baseline: 1.3564x; 1.3564x over previous
#include <cuda_runtime.h>
#include <cuda_bf16.h>
#include <cstdint>

#define S_LEN   2048
#define BATCH   2
#define DMODEL  1024
#define NHEADS  16
#define DK      64
#define MTOT    (BATCH * S_LEN)   // 4096

// ---------------- scratch (static device globals; no dynamic allocation) ----
__device__ float g_Q[BATCH * NHEADS * S_LEN * DK];    // (b,h,s,d)
__device__ float g_K[BATCH * NHEADS * S_LEN * DK];
__device__ float g_V[BATCH * NHEADS * S_LEN * DK];
__device__ float g_ctx[MTOT * DMODEL];                // (b,s,h*d)

// ======================= warp-MMA helpers (portable PTX) ====================
__device__ __forceinline__ uint32_t smem_u32(const void* p) {
    uint32_t a;
    asm("{ .reg .u64 t; cvta.to.shared.u64 t, %1; cvt.u32.u64 %0, t; }"
        : "=r"(a) : "l"(p));
    return a;
}

#define LDSM_X4(r0, r1, r2, r3, addr) \
    asm volatile("ldmatrix.sync.aligned.m8n8.x4.shared.b16 {%0,%1,%2,%3}, [%4];" \
                 : "=r"(r0), "=r"(r1), "=r"(r2), "=r"(r3) : "r"(addr))

#define MMA_BF16(d, a, b0, b1) \
    asm volatile("mma.sync.aligned.m16n8k16.row.col.f32.bf16.bf16.f32 " \
                 "{%0,%1,%2,%3}, {%4,%5,%6,%7}, {%8,%9}, {%0,%1,%2,%3};" \
                 : "+f"((d)[0]), "+f"((d)[1]), "+f"((d)[2]), "+f"((d)[3]) \
                 : "r"((a)[0]), "r"((a)[1]), "r"((a)[2]), "r"((a)[3]), \
                   "r"(b0), "r"(b1))

// split one float4 into packed-bf16 hi pair and lo (residual) pair
__device__ __forceinline__ void split_f4(float4 v, uint2& hi, uint2& lo) {
    uint32_t hA, hB, lA, lB;
    asm("cvt.rn.bf16x2.f32 %0, %1, %2;" : "=r"(hA) : "f"(v.y), "f"(v.x));
    asm("cvt.rn.bf16x2.f32 %0, %1, %2;" : "=r"(hB) : "f"(v.w), "f"(v.z));
    float f0 = __uint_as_float(hA << 16), f1 = __uint_as_float(hA & 0xFFFF0000u);
    float f2 = __uint_as_float(hB << 16), f3 = __uint_as_float(hB & 0xFFFF0000u);
    asm("cvt.rn.bf16x2.f32 %0, %1, %2;" : "=r"(lA) : "f"(v.y - f1), "f"(v.x - f0));
    asm("cvt.rn.bf16x2.f32 %0, %1, %2;" : "=r"(lB) : "f"(v.w - f3), "f"(v.z - f2));
    hi = make_uint2(hA, hB);
    lo = make_uint2(lA, lB);
}

// ======================= HMMA split-bf16 GEMM ==============================
// C[4096,1024] = A @ W^T + bias (fp32 in/out). CTA 128x128, warp 64x32,
// K-chunk 32 (two k16 slices), double-buffered bf16 smem hi/lo.
// Row layout: 16 bf16 padded to 48B pitch -> conflict-free ldmatrix.
// NOTE: W[n][k] row-major pairs consecutive k for fixed n == exactly the
// mma.row.col B-fragment layout, so W uses PLAIN ldmatrix (no .trans).
#define PITCH_B   48                          // bytes per 16-bf16 row slot
#define SL_SZ     6144                        // 128 rows * 48B, one k16 slice
#define AH_OFF    0
#define AL_OFF    12288
#define WH_OFF    24576
#define WL_OFF    36864
#define BUF_SZ    49152
#define GEMM_SMEM (2 * BUF_SZ)                // 98304

template <int MODE>
__global__ void __launch_bounds__(256, 2) gemm_mma(
    const float* __restrict__ A, const float* __restrict__ W,
    const float* __restrict__ bias, float* __restrict__ C)
{
    extern __shared__ __align__(128) char smem[];
    const uint32_t sb = smem_u32(smem);
    const int tid  = threadIdx.x;
    const int lane = tid & 31;
    const int wid  = tid >> 5;
    const int wm   = wid >> 2;               // 0..1  (64-row slab)
    const int wn   = wid & 3;                // 0..3  (32-col slab)
    const int m0   = blockIdx.y * 128;
    const int n0   = blockIdx.x * 128;

    const uint32_t laneOff = (uint32_t)((lane & 15) * PITCH_B + (lane >> 4) * 16);

    float acc[4][4][4];
#pragma unroll
    for (int i = 0; i < 4; ++i)
#pragma unroll
        for (int j = 0; j < 4; ++j)
#pragma unroll
            for (int r = 0; r < 4; ++r) acc[i][j][r] = 0.0f;

#pragma unroll 1
    for (int ch = 0; ch < 32; ++ch) {
        const int kt = ch * 32;
        char* sp = smem + (ch & 1) * BUF_SZ;

        // ---- load fp32, split to bf16 hi/lo, store to smem ----
#pragma unroll
        for (int i = 0; i < 4; ++i) {
            int slot = i * 256 + tid;
            int row  = slot >> 3;
            int q    = (slot & 7) << 2;            // k offset 0..28
            int soff = (q >> 4) * SL_SZ + row * PITCH_B + (q & 15) * 2;
            uint2 hi, lo;
            split_f4(*(const float4*)(A + (size_t)(m0 + row) * DMODEL + kt + q), hi, lo);
            *(uint2*)(sp + AH_OFF + soff) = hi;
            *(uint2*)(sp + AL_OFF + soff) = lo;
            split_f4(*(const float4*)(W + (size_t)(n0 + row) * DMODEL + kt + q), hi, lo);
            *(uint2*)(sp + WH_OFF + soff) = hi;
            *(uint2*)(sp + WL_OFF + soff) = lo;
        }
        __syncthreads();

        const uint32_t bufb = sb + (ch & 1) * BUF_SZ;
        const uint32_t aBase = bufb + (uint32_t)(wm * 64) * PITCH_B + laneOff;
        const uint32_t wBase = bufb + (uint32_t)(wn * 32) * PITCH_B + laneOff;

#pragma unroll
        for (int ks = 0; ks < 2; ++ks) {
            const uint32_t so = (uint32_t)ks * SL_SZ;
            uint32_t ah[4][4], wh[2][4], tmp[2][4];
#pragma unroll
            for (int mt = 0; mt < 4; ++mt)
                LDSM_X4(ah[mt][0], ah[mt][1], ah[mt][2], ah[mt][3],
                        aBase + AH_OFF + so + mt * 16 * PITCH_B);
#pragma unroll
            for (int n2 = 0; n2 < 2; ++n2)
                LDSM_X4(wh[n2][0], wh[n2][1], wh[n2][2], wh[n2][3],
                        wBase + WH_OFF + so + n2 * 16 * PITCH_B);
            // term 1: Ah * Wh
#pragma unroll
            for (int mt = 0; mt < 4; ++mt)
#pragma unroll
                for (int nt = 0; nt < 4; ++nt)
                    MMA_BF16(acc[mt][nt], ah[mt],
                             wh[nt >> 1][nt & 1], wh[nt >> 1][(nt & 1) + 2]);
            // term 2: Ah * Wl
#pragma unroll
            for (int n2 = 0; n2 < 2; ++n2)
                LDSM_X4(tmp[n2][0], tmp[n2][1], tmp[n2][2], tmp[n2][3],
                        wBase + WL_OFF + so + n2 * 16 * PITCH_B);
#pragma unroll
            for (int mt = 0; mt < 4; ++mt)
#pragma unroll
                for (int nt = 0; nt < 4; ++nt)
                    MMA_BF16(acc[mt][nt], ah[mt],
                             tmp[nt >> 1][nt & 1], tmp[nt >> 1][(nt & 1) + 2]);
            // term 3: Al * Wh
#pragma unroll
            for (int mt = 0; mt < 4; ++mt) {
                uint32_t al[4];
                LDSM_X4(al[0], al[1], al[2], al[3],
                        aBase + AL_OFF + so + mt * 16 * PITCH_B);
#pragma unroll
                for (int nt = 0; nt < 4; ++nt)
                    MMA_BF16(acc[mt][nt], al,
                             wh[nt >> 1][nt & 1], wh[nt >> 1][(nt & 1) + 2]);
            }
        }
        __syncthreads();
    }

    // ---- epilogue: fragment -> global with bias ----
    const int group = lane >> 2;
    const int tcol  = (lane & 3) * 2;
#pragma unroll
    for (int mt = 0; mt < 4; ++mt) {
#pragma unroll
        for (int nt = 0; nt < 4; ++nt) {
            int row = m0 + wm * 64 + mt * 16 + group;
            int col = n0 + wn * 32 + nt * 8 + tcol;
            float bx = bias[col], by = bias[col + 1];
            float2 v0 = make_float2(acc[mt][nt][0] + bx, acc[mt][nt][1] + by);
            float2 v1 = make_float2(acc[mt][nt][2] + bx, acc[mt][nt][3] + by);
            if (MODE == 0) {
                *(float2*)(C + (size_t)row * DMODEL + col) = v0;
                *(float2*)(C + (size_t)(row + 8) * DMODEL + col) = v1;
            } else {
                int h = col >> 6, d = col & 63;
                int b0_ = row >> 11, s0_ = row & 2047;
                int b1_ = (row + 8) >> 11, s1_ = (row + 8) & 2047;
                *(float2*)(C + (((size_t)(b0_ * NHEADS + h) * S_LEN + s0_) * DK) + d) = v0;
                *(float2*)(C + (((size_t)(b1_ * NHEADS + h) * S_LEN + s1_) * DK) + d) = v1;
            }
        }
    }
}

// ======================= flash attention (fp32 SIMT, unchanged) ============
__global__ void __launch_bounds__(256, 2) attn_kernel(
    const float* __restrict__ Q, const float* __restrict__ K,
    const float* __restrict__ V, const int* __restrict__ mask,
    float* __restrict__ ctx)
{
    __shared__ float Qt[DK][64];     // [d][q]
    __shared__ float KPt[64][64];    // K: [d][k]  /  P: [k][q]
    __shared__ float Vs[64][DK];     // [k][d]

    const int qt = blockIdx.x;
    const int h  = blockIdx.y;
    const int b  = blockIdx.z;
    const int q0 = qt * 64;
    const size_t base = (size_t)(b * NHEADS + h) * S_LEN * DK;

    const int tid = threadIdx.x;
    const int tx = tid & 15;
    const int ty = tid >> 4;

#pragma unroll
    for (int i = 0; i < 4; ++i) {
        int v = tid * 4 + i;
        int q = v >> 4;
        int d = (v & 15) << 2;
        float4 x = *(const float4*)(Q + base + (size_t)(q0 + q) * DK + d);
        Qt[d + 0][q] = x.x; Qt[d + 1][q] = x.y;
        Qt[d + 2][q] = x.z; Qt[d + 3][q] = x.w;
    }

    float m_i[4], l_i[4], o[4][4];
#pragma unroll
    for (int qi = 0; qi < 4; ++qi) {
        m_i[qi] = -1.0e30f;
        l_i[qi] = 0.0f;
#pragma unroll
        for (int dj = 0; dj < 4; ++dj) o[qi][dj] = 0.0f;
    }

    for (int k0 = 0; k0 < S_LEN; k0 += 64) {
#pragma unroll
        for (int i = 0; i < 4; ++i) {
            int v = tid * 4 + i;
            int r = v >> 4;
            int d = (v & 15) << 2;
            float4 kk = *(const float4*)(K + base + (size_t)(k0 + r) * DK + d);
            KPt[d + 0][r] = kk.x; KPt[d + 1][r] = kk.y;
            KPt[d + 2][r] = kk.z; KPt[d + 3][r] = kk.w;
            float4 vv = *(const float4*)(V + base + (size_t)(k0 + r) * DK + d);
            *(float4*)&Vs[r][d] = vv;
        }
        int4 mk = *(const int4*)(mask + b * S_LEN + k0 + tx * 4);
        __syncthreads();

        float s[4][4];
#pragma unroll
        for (int qi = 0; qi < 4; ++qi)
#pragma unroll
            for (int kj = 0; kj < 4; ++kj) s[qi][kj] = 0.0f;
#pragma unroll
        for (int d = 0; d < DK; ++d) {
            float4 rq = *(float4*)&Qt[d][ty * 4];
            float4 rk = *(float4*)&KPt[d][tx * 4];
            float fq[4] = {rq.x, rq.y, rq.z, rq.w};
            float fk[4] = {rk.x, rk.y, rk.z, rk.w};
#pragma unroll
            for (int qi = 0; qi < 4; ++qi)
#pragma unroll
                for (int kj = 0; kj < 4; ++kj) s[qi][kj] += fq[qi] * fk[kj];
        }
        const float scale = 0.125f;
        int msk[4] = {mk.x, mk.y, mk.z, mk.w};
#pragma unroll
        for (int qi = 0; qi < 4; ++qi)
#pragma unroll
            for (int kj = 0; kj < 4; ++kj) {
                float v = s[qi][kj] * scale;
                s[qi][kj] = (msk[kj] == 0) ? -1.0e9f : v;
            }

        float alpha[4];
#pragma unroll
        for (int qi = 0; qi < 4; ++qi) {
            float mx = fmaxf(fmaxf(s[qi][0], s[qi][1]), fmaxf(s[qi][2], s[qi][3]));
#pragma unroll
            for (int off = 8; off >= 1; off >>= 1)
                mx = fmaxf(mx, __shfl_xor_sync(0xffffffffu, mx, off));
            float mn = fmaxf(m_i[qi], mx);
            float rs = 0.0f;
#pragma unroll
            for (int kj = 0; kj < 4; ++kj) {
                s[qi][kj] = __expf(s[qi][kj] - mn);
                rs += s[qi][kj];
            }
#pragma unroll
            for (int off = 8; off >= 1; off >>= 1)
                rs += __shfl_xor_sync(0xffffffffu, rs, off);
            alpha[qi] = __expf(m_i[qi] - mn);
            l_i[qi] = l_i[qi] * alpha[qi] + rs;
            m_i[qi] = mn;
        }

        __syncthreads();
#pragma unroll
        for (int kj = 0; kj < 4; ++kj) {
            *(float4*)&KPt[tx * 4 + kj][ty * 4] =
                make_float4(s[0][kj], s[1][kj], s[2][kj], s[3][kj]);
        }
        __syncthreads();

#pragma unroll
        for (int qi = 0; qi < 4; ++qi)
#pragma unroll
            for (int dj = 0; dj < 4; ++dj) o[qi][dj] *= alpha[qi];
#pragma unroll
        for (int k = 0; k < 64; ++k) {
            float4 rp = *(float4*)&KPt[k][ty * 4];
            float4 rv = *(float4*)&Vs[k][tx * 4];
            float fp[4] = {rp.x, rp.y, rp.z, rp.w};
            float fv[4] = {rv.x, rv.y, rv.z, rv.w};
#pragma unroll
            for (int qi = 0; qi < 4; ++qi)
#pragma unroll
                for (int dj = 0; dj < 4; ++dj) o[qi][dj] += fp[qi] * fv[dj];
        }
        __syncthreads();
    }

#pragma unroll
    for (int qi = 0; qi < 4; ++qi) {
        float inv = 1.0f / l_i[qi];
        int q = q0 + ty * 4 + qi;
        float4 out = make_float4(o[qi][0] * inv, o[qi][1] * inv,
                                 o[qi][2] * inv, o[qi][3] * inv);
        *(float4*)(ctx + (size_t)(b * S_LEN + q) * DMODEL + h * DK + tx * 4) = out;
    }
}

// ---------------------------------------------------------------------------
extern "C" void kernel_launch(void* const* d_in, const int* in_sizes, int n_in,
                              void* d_out, int out_size)
{
    const float* query = (const float*)d_in[0];
    const float* key   = (const float*)d_in[1];
    const float* value = (const float*)d_in[2];
    const int*   mask  = (const int*)d_in[3];
    const float* Wq = (const float*)d_in[4];
    const float* bq = (const float*)d_in[5];
    const float* Wk = (const float*)d_in[6];
    const float* bk = (const float*)d_in[7];
    const float* Wv = (const float*)d_in[8];
    const float* bv = (const float*)d_in[9];
    const float* Wo = (const float*)d_in[10];
    const float* bo = (const float*)d_in[11];
    float* out = (float*)d_out;

    float *Qd, *Kd, *Vd, *Cd;
    cudaGetSymbolAddress((void**)&Qd, g_Q);
    cudaGetSymbolAddress((void**)&Kd, g_K);
    cudaGetSymbolAddress((void**)&Vd, g_V);
    cudaGetSymbolAddress((void**)&Cd, g_ctx);

    cudaFuncSetAttribute(gemm_mma<0>, cudaFuncAttributeMaxDynamicSharedMemorySize, GEMM_SMEM);
    cudaFuncSetAttribute(gemm_mma<1>, cudaFuncAttributeMaxDynamicSharedMemorySize, GEMM_SMEM);

    dim3 gg(DMODEL / 128, MTOT / 128);          // (8, 32) = 256 CTAs
    gemm_mma<1><<<gg, 256, GEMM_SMEM>>>(query, Wq, bq, Qd);
    gemm_mma<1><<<gg, 256, GEMM_SMEM>>>(key,   Wk, bk, Kd);
    gemm_mma<1><<<gg, 256, GEMM_SMEM>>>(value, Wv, bv, Vd);

    dim3 attn_grid(S_LEN / 64, NHEADS, BATCH);  // (32, 16, 2)
    attn_kernel<<<attn_grid, 256>>>(Qd, Kd, Vd, mask, Cd);

    gemm_mma<0><<<gg, 256, GEMM_SMEM>>>(Cd, Wo, bo, out);
}

// round 5
// speedup vs baseline: 2.7685x; 2.0410x over previous
#include <cuda_runtime.h>
#include <cuda_bf16.h>
#include <cstdint>

#define S_LEN   2048
#define BATCH   2
#define DMODEL  1024
#define NHEADS  16
#define DK      64
#define MTOT    (BATCH * S_LEN)   // 4096

// ---------------- scratch (static device globals; no dynamic allocation) ----
__device__ float g_Q[BATCH * NHEADS * S_LEN * DK];    // (b,h,s,d)
__device__ float g_K[BATCH * NHEADS * S_LEN * DK];
__device__ float g_V[BATCH * NHEADS * S_LEN * DK];
__device__ float g_ctx[MTOT * DMODEL];                // (b,s,h*d)

// ======================= warp-MMA helpers (portable PTX) ====================
__device__ __forceinline__ uint32_t smem_u32(const void* p) {
    uint32_t a;
    asm("{ .reg .u64 t; cvta.to.shared.u64 t, %1; cvt.u32.u64 %0, t; }"
        : "=r"(a) : "l"(p));
    return a;
}

#define LDSM_X4(r0, r1, r2, r3, addr) \
    asm volatile("ldmatrix.sync.aligned.m8n8.x4.shared.b16 {%0,%1,%2,%3}, [%4];" \
                 : "=r"(r0), "=r"(r1), "=r"(r2), "=r"(r3) : "r"(addr))

#define LDSM_X4_T(r0, r1, r2, r3, addr) \
    asm volatile("ldmatrix.sync.aligned.m8n8.x4.trans.shared.b16 {%0,%1,%2,%3}, [%4];" \
                 : "=r"(r0), "=r"(r1), "=r"(r2), "=r"(r3) : "r"(addr))

#define MMA_BF16(d, a, b0, b1) \
    asm volatile("mma.sync.aligned.m16n8k16.row.col.f32.bf16.bf16.f32 " \
                 "{%0,%1,%2,%3}, {%4,%5,%6,%7}, {%8,%9}, {%0,%1,%2,%3};" \
                 : "+f"((d)[0]), "+f"((d)[1]), "+f"((d)[2]), "+f"((d)[3]) \
                 : "r"((a)[0]), "r"((a)[1]), "r"((a)[2]), "r"((a)[3]), \
                   "r"(b0), "r"(b1))

// split one float4 into packed-bf16 hi pair and lo (residual) pair
__device__ __forceinline__ void split_f4(float4 v, uint2& hi, uint2& lo) {
    uint32_t hA, hB, lA, lB;
    asm("cvt.rn.bf16x2.f32 %0, %1, %2;" : "=r"(hA) : "f"(v.y), "f"(v.x));
    asm("cvt.rn.bf16x2.f32 %0, %1, %2;" : "=r"(hB) : "f"(v.w), "f"(v.z));
    float f0 = __uint_as_float(hA << 16), f1 = __uint_as_float(hA & 0xFFFF0000u);
    float f2 = __uint_as_float(hB << 16), f3 = __uint_as_float(hB & 0xFFFF0000u);
    asm("cvt.rn.bf16x2.f32 %0, %1, %2;" : "=r"(lA) : "f"(v.y - f1), "f"(v.x - f0));
    asm("cvt.rn.bf16x2.f32 %0, %1, %2;" : "=r"(lB) : "f"(v.w - f3), "f"(v.z - f2));
    hi = make_uint2(hA, hB);
    lo = make_uint2(lA, lB);
}

// split two fp32 into one bf16x2 hi word + one bf16x2 lo (residual) word
__device__ __forceinline__ void split2(float a, float b, uint32_t& hi, uint32_t& lo) {
    asm("cvt.rn.bf16x2.f32 %0, %1, %2;" : "=r"(hi) : "f"(b), "f"(a));
    float fa = __uint_as_float(hi << 16), fb = __uint_as_float(hi & 0xFFFF0000u);
    asm("cvt.rn.bf16x2.f32 %0, %1, %2;" : "=r"(lo) : "f"(b - fb), "f"(a - fa));
}

// ======================= HMMA split-bf16 GEMM (unchanged, passing) =========
#define PITCH_B   48
#define SL_SZ     6144
#define AH_OFF    0
#define AL_OFF    12288
#define WH_OFF    24576
#define WL_OFF    36864
#define BUF_SZ    49152
#define GEMM_SMEM (2 * BUF_SZ)

template <int MODE>
__global__ void __launch_bounds__(256, 2) gemm_mma(
    const float* __restrict__ A, const float* __restrict__ W,
    const float* __restrict__ bias, float* __restrict__ C)
{
    extern __shared__ __align__(128) char smem[];
    const uint32_t sb = smem_u32(smem);
    const int tid  = threadIdx.x;
    const int lane = tid & 31;
    const int wid  = tid >> 5;
    const int wm   = wid >> 2;
    const int wn   = wid & 3;
    const int m0   = blockIdx.y * 128;
    const int n0   = blockIdx.x * 128;

    const uint32_t laneOff = (uint32_t)((lane & 15) * PITCH_B + (lane >> 4) * 16);

    float acc[4][4][4];
#pragma unroll
    for (int i = 0; i < 4; ++i)
#pragma unroll
        for (int j = 0; j < 4; ++j)
#pragma unroll
            for (int r = 0; r < 4; ++r) acc[i][j][r] = 0.0f;

#pragma unroll 1
    for (int ch = 0; ch < 32; ++ch) {
        const int kt = ch * 32;
        char* sp = smem + (ch & 1) * BUF_SZ;

#pragma unroll
        for (int i = 0; i < 4; ++i) {
            int slot = i * 256 + tid;
            int row  = slot >> 3;
            int q    = (slot & 7) << 2;
            int soff = (q >> 4) * SL_SZ + row * PITCH_B + (q & 15) * 2;
            uint2 hi, lo;
            split_f4(*(const float4*)(A + (size_t)(m0 + row) * DMODEL + kt + q), hi, lo);
            *(uint2*)(sp + AH_OFF + soff) = hi;
            *(uint2*)(sp + AL_OFF + soff) = lo;
            split_f4(*(const float4*)(W + (size_t)(n0 + row) * DMODEL + kt + q), hi, lo);
            *(uint2*)(sp + WH_OFF + soff) = hi;
            *(uint2*)(sp + WL_OFF + soff) = lo;
        }
        __syncthreads();

        const uint32_t bufb = sb + (ch & 1) * BUF_SZ;
        const uint32_t aBase = bufb + (uint32_t)(wm * 64) * PITCH_B + laneOff;
        const uint32_t wBase = bufb + (uint32_t)(wn * 32) * PITCH_B + laneOff;

#pragma unroll
        for (int ks = 0; ks < 2; ++ks) {
            const uint32_t so = (uint32_t)ks * SL_SZ;
            uint32_t ah[4][4], wh[2][4], tmp[2][4];
#pragma unroll
            for (int mt = 0; mt < 4; ++mt)
                LDSM_X4(ah[mt][0], ah[mt][1], ah[mt][2], ah[mt][3],
                        aBase + AH_OFF + so + mt * 16 * PITCH_B);
#pragma unroll
            for (int n2 = 0; n2 < 2; ++n2)
                LDSM_X4(wh[n2][0], wh[n2][1], wh[n2][2], wh[n2][3],
                        wBase + WH_OFF + so + n2 * 16 * PITCH_B);
#pragma unroll
            for (int mt = 0; mt < 4; ++mt)
#pragma unroll
                for (int nt = 0; nt < 4; ++nt)
                    MMA_BF16(acc[mt][nt], ah[mt],
                             wh[nt >> 1][nt & 1], wh[nt >> 1][(nt & 1) + 2]);
#pragma unroll
            for (int n2 = 0; n2 < 2; ++n2)
                LDSM_X4(tmp[n2][0], tmp[n2][1], tmp[n2][2], tmp[n2][3],
                        wBase + WL_OFF + so + n2 * 16 * PITCH_B);
#pragma unroll
            for (int mt = 0; mt < 4; ++mt)
#pragma unroll
                for (int nt = 0; nt < 4; ++nt)
                    MMA_BF16(acc[mt][nt], ah[mt],
                             tmp[nt >> 1][nt & 1], tmp[nt >> 1][(nt & 1) + 2]);
#pragma unroll
            for (int mt = 0; mt < 4; ++mt) {
                uint32_t al[4];
                LDSM_X4(al[0], al[1], al[2], al[3],
                        aBase + AL_OFF + so + mt * 16 * PITCH_B);
#pragma unroll
                for (int nt = 0; nt < 4; ++nt)
                    MMA_BF16(acc[mt][nt], al,
                             wh[nt >> 1][nt & 1], wh[nt >> 1][(nt & 1) + 2]);
            }
        }
        __syncthreads();
    }

    const int group = lane >> 2;
    const int tcol  = (lane & 3) * 2;
#pragma unroll
    for (int mt = 0; mt < 4; ++mt) {
#pragma unroll
        for (int nt = 0; nt < 4; ++nt) {
            int row = m0 + wm * 64 + mt * 16 + group;
            int col = n0 + wn * 32 + nt * 8 + tcol;
            float bx = bias[col], by = bias[col + 1];
            float2 v0 = make_float2(acc[mt][nt][0] + bx, acc[mt][nt][1] + by);
            float2 v1 = make_float2(acc[mt][nt][2] + bx, acc[mt][nt][3] + by);
            if (MODE == 0) {
                *(float2*)(C + (size_t)row * DMODEL + col) = v0;
                *(float2*)(C + (size_t)(row + 8) * DMODEL + col) = v1;
            } else {
                int h = col >> 6, d = col & 63;
                int b0_ = row >> 11, s0_ = row & 2047;
                int b1_ = (row + 8) >> 11, s1_ = (row + 8) & 2047;
                *(float2*)(C + (((size_t)(b0_ * NHEADS + h) * S_LEN + s0_) * DK) + d) = v0;
                *(float2*)(C + (((size_t)(b1_ * NHEADS + h) * S_LEN + s1_) * DK) + d) = v1;
            }
        }
    }
}

// ======================= HMMA flash attention ==============================
// CTA: 128 q rows (8 warps x 16), k-tiles of 64, double-buffered split-bf16
// K/V in smem (pitch 144B = conflict-free ldmatrix). Q pre-scaled by 1/8,
// fragments register-resident. P stays in registers (acc layout == A layout).
#define APITCH    144
#define KHI_OFF   0
#define KLO_OFF   9216
#define VHI_OFF   18432
#define VLO_OFF   27648
#define KVBUF_SZ  36864
#define QHI_OFF   73728
#define QLO_OFF   92160
#define MASK_OFF  110592
#define ATTN_SMEM (MASK_OFF + 2 * 64 * 4)   // 111104

__global__ void __launch_bounds__(256) attn_mma(
    const float* __restrict__ Q, const float* __restrict__ K,
    const float* __restrict__ V, const int* __restrict__ mask,
    float* __restrict__ ctx)
{
    extern __shared__ __align__(128) char smem[];
    const uint32_t sb = smem_u32(smem);
    const int tid  = threadIdx.x;
    const int lane = tid & 31;
    const int wid  = tid >> 5;
    const int q0   = blockIdx.x * 128;
    const int h    = blockIdx.y;
    const int b    = blockIdx.z;
    const size_t base = (size_t)(b * NHEADS + h) * S_LEN * DK;

    const uint32_t laneOff = (uint32_t)((lane & 15) * APITCH + (lane >> 4) * 16);

    // ---- stage Q (scaled by 1/8), split hi/lo ----
#pragma unroll
    for (int i = 0; i < 8; ++i) {
        int slot = i * 256 + tid;
        int row  = slot >> 4;
        int dq   = (slot & 15) << 2;
        float4 v = *(const float4*)(Q + base + (size_t)(q0 + row) * DK + dq);
        v.x *= 0.125f; v.y *= 0.125f; v.z *= 0.125f; v.w *= 0.125f;
        uint2 hi, lo;
        split_f4(v, hi, lo);
        int soff = row * APITCH + dq * 2;
        *(uint2*)(smem + QHI_OFF + soff) = hi;
        *(uint2*)(smem + QLO_OFF + soff) = lo;
    }
    __syncthreads();

    // ---- Q fragments (register-resident) ----
    uint32_t qh[4][4], ql[4][4];
    {
        const uint32_t qbH = sb + QHI_OFF + (uint32_t)(wid * 16) * APITCH + laneOff;
        const uint32_t qbL = sb + QLO_OFF + (uint32_t)(wid * 16) * APITCH + laneOff;
#pragma unroll
        for (int s = 0; s < 4; ++s) {
            LDSM_X4(qh[s][0], qh[s][1], qh[s][2], qh[s][3], qbH + s * 32);
            LDSM_X4(ql[s][0], ql[s][1], ql[s][2], ql[s][3], qbL + s * 32);
        }
    }

    float o[8][4];
#pragma unroll
    for (int dt = 0; dt < 8; ++dt)
#pragma unroll
        for (int r = 0; r < 4; ++r) o[dt][r] = 0.0f;
    float mi0 = -1.0e30f, mi1 = -1.0e30f, li0 = 0.0f, li1 = 0.0f;

#pragma unroll 1
    for (int t = 0; t < 32; ++t) {
        const int k0 = t * 64;
        const int buf = t & 1;
        char* sp = smem + buf * KVBUF_SZ;

        // ---- load K/V tile, split hi/lo ----
#pragma unroll
        for (int i = 0; i < 4; ++i) {
            int slot = i * 256 + tid;
            int row  = slot >> 4;
            int dq   = (slot & 15) << 2;
            int soff = row * APITCH + dq * 2;
            uint2 hi, lo;
            split_f4(*(const float4*)(K + base + (size_t)(k0 + row) * DK + dq), hi, lo);
            *(uint2*)(sp + KHI_OFF + soff) = hi;
            *(uint2*)(sp + KLO_OFF + soff) = lo;
            split_f4(*(const float4*)(V + base + (size_t)(k0 + row) * DK + dq), hi, lo);
            *(uint2*)(sp + VHI_OFF + soff) = hi;
            *(uint2*)(sp + VLO_OFF + soff) = lo;
        }
        if (tid < 64)
            ((int*)(smem + MASK_OFF))[buf * 64 + tid] = mask[b * S_LEN + k0 + tid];
        __syncthreads();

        // ---- S = Q K^T (3-term split) ----
        float s_[8][4];
#pragma unroll
        for (int nt = 0; nt < 8; ++nt)
#pragma unroll
            for (int r = 0; r < 4; ++r) s_[nt][r] = 0.0f;

        const uint32_t kB = sb + (uint32_t)(buf * KVBUF_SZ) + laneOff;
#pragma unroll
        for (int st = 0; st < 4; ++st) {
#pragma unroll
            for (int g2 = 0; g2 < 4; ++g2) {
                uint32_t kh[4], kl[4];
                LDSM_X4(kh[0], kh[1], kh[2], kh[3],
                        kB + KHI_OFF + g2 * (16 * APITCH) + st * 32);
                LDSM_X4(kl[0], kl[1], kl[2], kl[3],
                        kB + KLO_OFF + g2 * (16 * APITCH) + st * 32);
                MMA_BF16(s_[2 * g2],     qh[st], kh[0], kh[2]);
                MMA_BF16(s_[2 * g2 + 1], qh[st], kh[1], kh[3]);
                MMA_BF16(s_[2 * g2],     qh[st], kl[0], kl[2]);
                MMA_BF16(s_[2 * g2 + 1], qh[st], kl[1], kl[3]);
                MMA_BF16(s_[2 * g2],     ql[st], kh[0], kh[2]);
                MMA_BF16(s_[2 * g2 + 1], ql[st], kh[1], kh[3]);
            }
        }

        // ---- mask ----
        const int* mbuf = (const int*)(smem + MASK_OFF) + buf * 64;
#pragma unroll
        for (int nt = 0; nt < 8; ++nt) {
            int2 mv = *(const int2*)&mbuf[nt * 8 + (lane & 3) * 2];
            if (mv.x == 0) { s_[nt][0] = -1.0e9f; s_[nt][2] = -1.0e9f; }
            if (mv.y == 0) { s_[nt][1] = -1.0e9f; s_[nt][3] = -1.0e9f; }
        }

        // ---- online softmax (rows g, g+8) ----
        float mx0 = -1.0e30f, mx1 = -1.0e30f;
#pragma unroll
        for (int nt = 0; nt < 8; ++nt) {
            mx0 = fmaxf(mx0, fmaxf(s_[nt][0], s_[nt][1]));
            mx1 = fmaxf(mx1, fmaxf(s_[nt][2], s_[nt][3]));
        }
        mx0 = fmaxf(mx0, __shfl_xor_sync(0xffffffffu, mx0, 1));
        mx0 = fmaxf(mx0, __shfl_xor_sync(0xffffffffu, mx0, 2));
        mx1 = fmaxf(mx1, __shfl_xor_sync(0xffffffffu, mx1, 1));
        mx1 = fmaxf(mx1, __shfl_xor_sync(0xffffffffu, mx1, 2));
        const float mn0 = fmaxf(mi0, mx0), mn1 = fmaxf(mi1, mx1);
        const float a0 = __expf(mi0 - mn0), a1 = __expf(mi1 - mn1);
        mi0 = mn0; mi1 = mn1;

        float sum0 = 0.0f, sum1 = 0.0f;
#pragma unroll
        for (int nt = 0; nt < 8; ++nt) {
            s_[nt][0] = __expf(s_[nt][0] - mn0);
            s_[nt][1] = __expf(s_[nt][1] - mn0);
            s_[nt][2] = __expf(s_[nt][2] - mn1);
            s_[nt][3] = __expf(s_[nt][3] - mn1);
            sum0 += s_[nt][0] + s_[nt][1];
            sum1 += s_[nt][2] + s_[nt][3];
        }
        sum0 += __shfl_xor_sync(0xffffffffu, sum0, 1);
        sum0 += __shfl_xor_sync(0xffffffffu, sum0, 2);
        sum1 += __shfl_xor_sync(0xffffffffu, sum1, 1);
        sum1 += __shfl_xor_sync(0xffffffffu, sum1, 2);
        li0 = li0 * a0 + sum0;
        li1 = li1 * a1 + sum1;

#pragma unroll
        for (int dt = 0; dt < 8; ++dt) {
            o[dt][0] *= a0; o[dt][1] *= a0;
            o[dt][2] *= a1; o[dt][3] *= a1;
        }

        // ---- O += P V (3-term split); P packed from accumulators ----
        const uint32_t vB = sb + (uint32_t)(buf * KVBUF_SZ) + laneOff;
#pragma unroll
        for (int st = 0; st < 4; ++st) {
            uint32_t ph[4], pl[4];
            split2(s_[2 * st][0],     s_[2 * st][1],     ph[0], pl[0]);
            split2(s_[2 * st][2],     s_[2 * st][3],     ph[1], pl[1]);
            split2(s_[2 * st + 1][0], s_[2 * st + 1][1], ph[2], pl[2]);
            split2(s_[2 * st + 1][2], s_[2 * st + 1][3], ph[3], pl[3]);
#pragma unroll
            for (int j = 0; j < 4; ++j) {
                uint32_t vh[4], vl[4];
                LDSM_X4_T(vh[0], vh[1], vh[2], vh[3],
                          vB + VHI_OFF + st * (16 * APITCH) + j * 32);
                LDSM_X4_T(vl[0], vl[1], vl[2], vl[3],
                          vB + VLO_OFF + st * (16 * APITCH) + j * 32);
                MMA_BF16(o[2 * j],     ph, vh[0], vh[1]);
                MMA_BF16(o[2 * j + 1], ph, vh[2], vh[3]);
                MMA_BF16(o[2 * j],     ph, vl[0], vl[1]);
                MMA_BF16(o[2 * j + 1], ph, vl[2], vl[3]);
                MMA_BF16(o[2 * j],     pl, vh[0], vh[1]);
                MMA_BF16(o[2 * j + 1], pl, vh[2], vh[3]);
            }
        }
    }

    // ---- epilogue: normalize, write ctx (b, s, h*64+d) ----
    const int g  = lane >> 2;
    const int t2 = (lane & 3) * 2;
    const int row0 = q0 + wid * 16 + g;
    const int row1 = row0 + 8;
    const float inv0 = 1.0f / li0, inv1 = 1.0f / li1;
#pragma unroll
    for (int dt = 0; dt < 8; ++dt) {
        int col = h * DK + dt * 8 + t2;
        *(float2*)(ctx + (size_t)(b * S_LEN + row0) * DMODEL + col) =
            make_float2(o[dt][0] * inv0, o[dt][1] * inv0);
        *(float2*)(ctx + (size_t)(b * S_LEN + row1) * DMODEL + col) =
            make_float2(o[dt][2] * inv1, o[dt][3] * inv1);
    }
}

// ---------------------------------------------------------------------------
extern "C" void kernel_launch(void* const* d_in, const int* in_sizes, int n_in,
                              void* d_out, int out_size)
{
    const float* query = (const float*)d_in[0];
    const float* key   = (const float*)d_in[1];
    const float* value = (const float*)d_in[2];
    const int*   mask  = (const int*)d_in[3];
    const float* Wq = (const float*)d_in[4];
    const float* bq = (const float*)d_in[5];
    const float* Wk = (const float*)d_in[6];
    const float* bk = (const float*)d_in[7];
    const float* Wv = (const float*)d_in[8];
    const float* bv = (const float*)d_in[9];
    const float* Wo = (const float*)d_in[10];
    const float* bo = (const float*)d_in[11];
    float* out = (float*)d_out;

    float *Qd, *Kd, *Vd, *Cd;
    cudaGetSymbolAddress((void**)&Qd, g_Q);
    cudaGetSymbolAddress((void**)&Kd, g_K);
    cudaGetSymbolAddress((void**)&Vd, g_V);
    cudaGetSymbolAddress((void**)&Cd, g_ctx);

    cudaFuncSetAttribute(gemm_mma<0>, cudaFuncAttributeMaxDynamicSharedMemorySize, GEMM_SMEM);
    cudaFuncSetAttribute(gemm_mma<1>, cudaFuncAttributeMaxDynamicSharedMemorySize, GEMM_SMEM);
    cudaFuncSetAttribute(attn_mma, cudaFuncAttributeMaxDynamicSharedMemorySize, ATTN_SMEM);

    dim3 gg(DMODEL / 128, MTOT / 128);          // (8, 32) = 256 CTAs
    gemm_mma<1><<<gg, 256, GEMM_SMEM>>>(query, Wq, bq, Qd);
    gemm_mma<1><<<gg, 256, GEMM_SMEM>>>(key,   Wk, bk, Kd);
    gemm_mma<1><<<gg, 256, GEMM_SMEM>>>(value, Wv, bv, Vd);

    dim3 ag(S_LEN / 128, NHEADS, BATCH);        // (16, 16, 2) = 512 CTAs
    attn_mma<<<ag, 256, ATTN_SMEM>>>(Qd, Kd, Vd, mask, Cd);

    gemm_mma<0><<<gg, 256, GEMM_SMEM>>>(Cd, Wo, bo, out);
}